// round 1
// baseline (speedup 1.0000x reference)
#include <cuda_runtime.h>
#include <math.h>

#define DM   1024
#define NSEQ 2048
#define NB   2
#define NH   16
#define HD   64
#define MROWS (NB*NSEQ)   // 4096

// Scratch (allocation-free rule: __device__ globals)
__device__ float g_Q[NB*NH*NSEQ*HD];   // (b,h,n,d) 16MB
__device__ float g_K[NB*NH*NSEQ*HD];
__device__ float g_V[NB*NH*NSEQ*HD];
__device__ float g_O[(size_t)MROWS*DM]; // (b*n, h*d) 16MB

// ---------------------------------------------------------------------------
// SGEMM NT core: C[m,n] = sum_k A[m,k]*B[n,k]; A (M,1024), B (N,1024) row-major
// BM=BN=128, BK=8, 256 threads, 8x8 per thread.
// ---------------------------------------------------------------------------

__global__ __launch_bounds__(256) void qkv_gemm(
    const float* __restrict__ Xq, const float* __restrict__ Xk, const float* __restrict__ Xv,
    const float* __restrict__ Wq, const float* __restrict__ bq,
    const float* __restrict__ Wk, const float* __restrict__ bk,
    const float* __restrict__ Wv, const float* __restrict__ bv)
{
    __shared__ float As[8][132];
    __shared__ float Bs[8][132];

    const float *X, *W, *Bias;
    float* Out;
    if (blockIdx.z == 0)      { X = Xq; W = Wq; Bias = bq; Out = g_Q; }
    else if (blockIdx.z == 1) { X = Xk; W = Wk; Bias = bk; Out = g_K; }
    else                      { X = Xv; W = Wv; Bias = bv; Out = g_V; }

    const int tid  = threadIdx.x;
    const int m0   = blockIdx.y * 128;
    const int n0   = blockIdx.x * 128;
    const int lrow = tid >> 1;          // 0..127
    const int lk   = (tid & 1) * 4;     // 0 or 4
    const int tx   = tid & 15;
    const int ty   = tid >> 4;

    const float* Ag = X + (size_t)(m0 + lrow) * DM + lk;
    const float* Bg = W + (size_t)(n0 + lrow) * DM + lk;

    float acc[8][8];
    #pragma unroll
    for (int i = 0; i < 8; i++)
        #pragma unroll
        for (int j = 0; j < 8; j++) acc[i][j] = 0.0f;

    for (int kt = 0; kt < DM; kt += 8) {
        float4 av = *(const float4*)(Ag + kt);
        float4 bv = *(const float4*)(Bg + kt);
        As[lk+0][lrow] = av.x; As[lk+1][lrow] = av.y;
        As[lk+2][lrow] = av.z; As[lk+3][lrow] = av.w;
        Bs[lk+0][lrow] = bv.x; Bs[lk+1][lrow] = bv.y;
        Bs[lk+2][lrow] = bv.z; Bs[lk+3][lrow] = bv.w;
        __syncthreads();

        #pragma unroll
        for (int k = 0; k < 8; k++) {
            float a[8], b[8];
            float4 t;
            t = *(const float4*)&As[k][ty*8    ]; a[0]=t.x; a[1]=t.y; a[2]=t.z; a[3]=t.w;
            t = *(const float4*)&As[k][ty*8 + 4]; a[4]=t.x; a[5]=t.y; a[6]=t.z; a[7]=t.w;
            t = *(const float4*)&Bs[k][tx*8    ]; b[0]=t.x; b[1]=t.y; b[2]=t.z; b[3]=t.w;
            t = *(const float4*)&Bs[k][tx*8 + 4]; b[4]=t.x; b[5]=t.y; b[6]=t.z; b[7]=t.w;
            #pragma unroll
            for (int i = 0; i < 8; i++)
                #pragma unroll
                for (int j = 0; j < 8; j++)
                    acc[i][j] += a[i] * b[j];
        }
        __syncthreads();
    }

    // Epilogue: scatter into (b, h, n, d) layout + bias
    #pragma unroll
    for (int i = 0; i < 8; i++) {
        int m  = m0 + ty*8 + i;
        int bb = m >> 11;            // / NSEQ
        int n  = m & (NSEQ - 1);
        #pragma unroll
        for (int j = 0; j < 8; j++) {
            int o = n0 + tx*8 + j;
            int h = o >> 6;
            int d = o & 63;
            Out[(((size_t)(bb*NH + h))*NSEQ + n)*HD + d] = acc[i][j] + Bias[o];
        }
    }
}

__global__ __launch_bounds__(256) void out_gemm(
    const float* __restrict__ Wo, const float* __restrict__ bo,
    float* __restrict__ C)
{
    __shared__ float As[8][132];
    __shared__ float Bs[8][132];

    const float* A = g_O;
    const int tid  = threadIdx.x;
    const int m0   = blockIdx.y * 128;
    const int n0   = blockIdx.x * 128;
    const int lrow = tid >> 1;
    const int lk   = (tid & 1) * 4;
    const int tx   = tid & 15;
    const int ty   = tid >> 4;

    const float* Ag = A  + (size_t)(m0 + lrow) * DM + lk;
    const float* Bg = Wo + (size_t)(n0 + lrow) * DM + lk;

    float acc[8][8];
    #pragma unroll
    for (int i = 0; i < 8; i++)
        #pragma unroll
        for (int j = 0; j < 8; j++) acc[i][j] = 0.0f;

    for (int kt = 0; kt < DM; kt += 8) {
        float4 av = *(const float4*)(Ag + kt);
        float4 bv = *(const float4*)(Bg + kt);
        As[lk+0][lrow] = av.x; As[lk+1][lrow] = av.y;
        As[lk+2][lrow] = av.z; As[lk+3][lrow] = av.w;
        Bs[lk+0][lrow] = bv.x; Bs[lk+1][lrow] = bv.y;
        Bs[lk+2][lrow] = bv.z; Bs[lk+3][lrow] = bv.w;
        __syncthreads();

        #pragma unroll
        for (int k = 0; k < 8; k++) {
            float a[8], b[8];
            float4 t;
            t = *(const float4*)&As[k][ty*8    ]; a[0]=t.x; a[1]=t.y; a[2]=t.z; a[3]=t.w;
            t = *(const float4*)&As[k][ty*8 + 4]; a[4]=t.x; a[5]=t.y; a[6]=t.z; a[7]=t.w;
            t = *(const float4*)&Bs[k][tx*8    ]; b[0]=t.x; b[1]=t.y; b[2]=t.z; b[3]=t.w;
            t = *(const float4*)&Bs[k][tx*8 + 4]; b[4]=t.x; b[5]=t.y; b[6]=t.z; b[7]=t.w;
            #pragma unroll
            for (int i = 0; i < 8; i++)
                #pragma unroll
                for (int j = 0; j < 8; j++)
                    acc[i][j] += a[i] * b[j];
        }
        __syncthreads();
    }

    #pragma unroll
    for (int i = 0; i < 8; i++) {
        int m = m0 + ty*8 + i;
        #pragma unroll
        for (int j = 0; j < 8; j++) {
            int o = n0 + tx*8 + j;
            C[(size_t)m*DM + o] = acc[i][j] + bo[o];
        }
    }
}

// ---------------------------------------------------------------------------
// Flash attention, fp32. One CTA = 64 query rows of one (b,h); loop 64-key tiles.
// 256 threads: tx=tid&15 (16 col-groups), ty=tid>>4 (16 row-groups), 4x4 micro.
// Row stats reduced via 16-lane shuffle (threads sharing a row are lanes
// {g*16 .. g*16+15} within a warp).
// ---------------------------------------------------------------------------
#define QST_STRIDE 68
#define FLASH_SMEM_FLOATS (64*68 /*Qst*/ + 64*68 /*Kst*/ + 64*64 /*Vs*/ + 64*68 /*Ps*/)
#define FLASH_SMEM_BYTES  (FLASH_SMEM_FLOATS * 4)

__global__ __launch_bounds__(256) void flash_kernel()
{
    extern __shared__ float sm[];
    float* Qst = sm;                    // [d][row]  stride 68
    float* Kst = Qst + 64*68;           // [d][col]  stride 68
    float* Vs  = Kst + 64*68;           // [key][d]  stride 64
    float* Ps  = Vs  + 64*64;           // [key][row] stride 68

    const int tid = threadIdx.x;
    const int tx  = tid & 15;
    const int ty  = tid >> 4;
    const int bh  = blockIdx.y;         // 0..31
    const int q0  = blockIdx.x * 64;

    const float* Qp = g_Q + (size_t)bh * NSEQ * HD + (size_t)q0 * HD;
    const float* Kp = g_K + (size_t)bh * NSEQ * HD;
    const float* Vp = g_V + (size_t)bh * NSEQ * HD;

    const float scale = 0.125f;  // 1/sqrt(64)

    // Load Q tile (64x64), transpose to [d][row], fold in softmax scale
    #pragma unroll
    for (int u = 0; u < 4; u++) {
        int idx = tid + u * 256;        // 0..1023 float4 slots
        int r   = idx >> 4;             // query row 0..63
        int d4  = (idx & 15) * 4;       // d offset
        float4 v = *(const float4*)(Qp + r*HD + d4);
        Qst[(d4+0)*QST_STRIDE + r] = v.x * scale;
        Qst[(d4+1)*QST_STRIDE + r] = v.y * scale;
        Qst[(d4+2)*QST_STRIDE + r] = v.z * scale;
        Qst[(d4+3)*QST_STRIDE + r] = v.w * scale;
    }

    float acc[4][4];
    float mrow[4], lrow[4];
    #pragma unroll
    for (int i = 0; i < 4; i++) {
        mrow[i] = -1e30f; lrow[i] = 0.0f;
        #pragma unroll
        for (int j = 0; j < 4; j++) acc[i][j] = 0.0f;
    }

    for (int kt = 0; kt < NSEQ / 64; kt++) {
        const float* Kt = Kp + (size_t)kt * 64 * HD;
        const float* Vt = Vp + (size_t)kt * 64 * HD;

        // Load K (transposed) and V (natural)
        #pragma unroll
        for (int u = 0; u < 4; u++) {
            int idx = tid + u * 256;
            int r   = idx >> 4;
            int d4  = (idx & 15) * 4;
            float4 kv = *(const float4*)(Kt + r*HD + d4);
            Kst[(d4+0)*QST_STRIDE + r] = kv.x;
            Kst[(d4+1)*QST_STRIDE + r] = kv.y;
            Kst[(d4+2)*QST_STRIDE + r] = kv.z;
            Kst[(d4+3)*QST_STRIDE + r] = kv.w;
            float4 vv = *(const float4*)(Vt + r*HD + d4);
            *(float4*)&Vs[r*64 + d4] = vv;
        }
        __syncthreads();

        // S = (Q*scale) K^T : 4x4 per thread, outer-product over d
        float s[4][4];
        #pragma unroll
        for (int i = 0; i < 4; i++)
            #pragma unroll
            for (int j = 0; j < 4; j++) s[i][j] = 0.0f;

        #pragma unroll 8
        for (int d = 0; d < 64; d++) {
            float4 a = *(const float4*)&Qst[d*QST_STRIDE + ty*4];
            float4 b = *(const float4*)&Kst[d*QST_STRIDE + tx*4];
            float aa[4] = {a.x, a.y, a.z, a.w};
            float bb[4] = {b.x, b.y, b.z, b.w};
            #pragma unroll
            for (int i = 0; i < 4; i++)
                #pragma unroll
                for (int j = 0; j < 4; j++)
                    s[i][j] += aa[i] * bb[j];
        }

        // Online softmax (rows owned by 16 lanes sharing ty)
        #pragma unroll
        for (int i = 0; i < 4; i++) {
            float rm = fmaxf(fmaxf(s[i][0], s[i][1]), fmaxf(s[i][2], s[i][3]));
            #pragma unroll
            for (int off = 8; off >= 1; off >>= 1)
                rm = fmaxf(rm, __shfl_xor_sync(0xffffffffu, rm, off));
            float mn   = fmaxf(mrow[i], rm);
            float corr = __expf(mrow[i] - mn);
            mrow[i] = mn;
            float rs = 0.0f;
            #pragma unroll
            for (int j = 0; j < 4; j++) {
                s[i][j] = __expf(s[i][j] - mn);
                rs += s[i][j];
            }
            #pragma unroll
            for (int off = 8; off >= 1; off >>= 1)
                rs += __shfl_xor_sync(0xffffffffu, rs, off);
            lrow[i] = lrow[i] * corr + rs;
            #pragma unroll
            for (int j = 0; j < 4; j++) acc[i][j] *= corr;
        }

        // Write P transposed: Ps[key][row], float4 along row
        #pragma unroll
        for (int j = 0; j < 4; j++) {
            float4 pv = make_float4(s[0][j], s[1][j], s[2][j], s[3][j]);
            *(float4*)&Ps[(tx*4 + j)*QST_STRIDE + ty*4] = pv;
        }
        __syncthreads();

        // acc += P^T-style GEMM: acc[i][j] += sum_k Ps[k][row_i] * Vs[k][col_j]
        #pragma unroll 8
        for (int k = 0; k < 64; k++) {
            float4 p = *(const float4*)&Ps[k*QST_STRIDE + ty*4];
            float4 v = *(const float4*)&Vs[k*64 + tx*4];
            float pp[4] = {p.x, p.y, p.z, p.w};
            float vv[4] = {v.x, v.y, v.z, v.w};
            #pragma unroll
            for (int i = 0; i < 4; i++)
                #pragma unroll
                for (int j = 0; j < 4; j++)
                    acc[i][j] += pp[i] * vv[j];
        }
        __syncthreads();
    }

    // Epilogue: out[b, n, h*64 + d] = acc / l
    const int b = bh >> 4;
    const int h = bh & 15;
    #pragma unroll
    for (int i = 0; i < 4; i++) {
        float inv = 1.0f / lrow[i];
        int n = q0 + ty*4 + i;
        float* orow = g_O + ((size_t)(b*NSEQ + n))*DM + h*HD + tx*4;
        float4 ov = make_float4(acc[i][0]*inv, acc[i][1]*inv, acc[i][2]*inv, acc[i][3]*inv);
        *(float4*)orow = ov;
    }
}

// ---------------------------------------------------------------------------
extern "C" void kernel_launch(void* const* d_in, const int* in_sizes, int n_in,
                              void* d_out, int out_size)
{
    (void)in_sizes; (void)n_in; (void)out_size;
    const float* queries = (const float*)d_in[0];
    const float* keys    = (const float*)d_in[1];
    const float* values  = (const float*)d_in[2];
    const float* Wq = (const float*)d_in[3];
    const float* bq = (const float*)d_in[4];
    const float* Wk = (const float*)d_in[5];
    const float* bk = (const float*)d_in[6];
    const float* Wv = (const float*)d_in[7];
    const float* bv = (const float*)d_in[8];
    const float* Wo = (const float*)d_in[9];
    const float* bo = (const float*)d_in[10];
    float* out = (float*)d_out;

    cudaFuncSetAttribute(flash_kernel,
                         cudaFuncAttributeMaxDynamicSharedMemorySize,
                         FLASH_SMEM_BYTES);

    // QKV projections: grid (N/128, M/128, 3)
    qkv_gemm<<<dim3(DM/128, MROWS/128, 3), 256>>>(
        queries, keys, values, Wq, bq, Wk, bk, Wv, bv);

    // Attention: grid (nq/64, b*h)
    flash_kernel<<<dim3(NSEQ/64, NB*NH), 256, FLASH_SMEM_BYTES>>>();

    // Output projection
    out_gemm<<<dim3(DM/128, MROWS/128), 256>>>(Wo, bo, out);
}

// round 2
// speedup vs baseline: 2.6730x; 2.6730x over previous
#include <cuda_runtime.h>
#include <cuda_bf16.h>
#include <math.h>

#define DM   1024
#define NSEQ 2048
#define NB   2
#define NH   16
#define HD   64
#define MROWS (NB*NSEQ)          // 4096
#define NELEM ((size_t)MROWS*DM) // 4,194,304
#define WELEM ((size_t)DM*DM)    // 1,048,576

// ---------------- scratch (__device__ globals; no allocations) -------------
__device__ __nv_bfloat16 gXh[3*NELEM];   // split inputs q,k,v
__device__ __nv_bfloat16 gXl[3*NELEM];
__device__ __nv_bfloat16 gWh[4*WELEM];   // split weights Wq,Wk,Wv,Wo
__device__ __nv_bfloat16 gWl[4*WELEM];
__device__ __nv_bfloat16 gQh[NELEM], gQl[NELEM];  // (b,h,n,d), Q pre-scaled
__device__ __nv_bfloat16 gKh[NELEM], gKl[NELEM];
__device__ __nv_bfloat16 gVh[NELEM], gVl[NELEM];
__device__ __nv_bfloat16 gOh[NELEM], gOl[NELEM];  // attn out (b*n, h*d)

// ---------------- PTX helpers ---------------------------------------------
__device__ __forceinline__ void mma16816(float* c,
    unsigned a0, unsigned a1, unsigned a2, unsigned a3,
    unsigned b0, unsigned b1)
{
    asm volatile(
        "mma.sync.aligned.m16n8k16.row.col.f32.bf16.bf16.f32 "
        "{%0,%1,%2,%3},{%4,%5,%6,%7},{%8,%9},{%0,%1,%2,%3};"
        : "+f"(c[0]), "+f"(c[1]), "+f"(c[2]), "+f"(c[3])
        : "r"(a0), "r"(a1), "r"(a2), "r"(a3), "r"(b0), "r"(b1));
}

__device__ __forceinline__ void ldm_x4(unsigned& r0, unsigned& r1,
                                       unsigned& r2, unsigned& r3,
                                       const __nv_bfloat16* p)
{
    unsigned a = (unsigned)__cvta_generic_to_shared(p);
    asm volatile("ldmatrix.sync.aligned.m8n8.x4.shared.b16 {%0,%1,%2,%3},[%4];"
                 : "=r"(r0), "=r"(r1), "=r"(r2), "=r"(r3) : "r"(a));
}

__device__ __forceinline__ void ldm_x2(unsigned& r0, unsigned& r1,
                                       const __nv_bfloat16* p)
{
    unsigned a = (unsigned)__cvta_generic_to_shared(p);
    asm volatile("ldmatrix.sync.aligned.m8n8.x2.shared.b16 {%0,%1},[%2];"
                 : "=r"(r0), "=r"(r1) : "r"(a));
}

__device__ __forceinline__ void ldm_x2t(unsigned& r0, unsigned& r1,
                                        const __nv_bfloat16* p)
{
    unsigned a = (unsigned)__cvta_generic_to_shared(p);
    asm volatile("ldmatrix.sync.aligned.m8n8.x2.trans.shared.b16 {%0,%1},[%2];"
                 : "=r"(r0), "=r"(r1) : "r"(a));
}

__device__ __forceinline__ void cp16(__nv_bfloat16* dst, const __nv_bfloat16* src)
{
    unsigned d = (unsigned)__cvta_generic_to_shared(dst);
    asm volatile("cp.async.cg.shared.global [%0], [%1], 16;" :: "r"(d), "l"(src));
}
#define CP_COMMIT() asm volatile("cp.async.commit_group;")

// split fp32 pair -> packed bf16x2 hi + bf16x2 lo
__device__ __forceinline__ void split_pack(float x, float y,
                                           unsigned& h, unsigned& l)
{
    __nv_bfloat16 hx = __float2bfloat16(x);
    __nv_bfloat16 hy = __float2bfloat16(y);
    float rx = x - __bfloat162float(hx);
    float ry = y - __bfloat162float(hy);
    __nv_bfloat16 lx = __float2bfloat16(rx);
    __nv_bfloat16 ly = __float2bfloat16(ry);
    h = ((unsigned)__bfloat16_as_ushort(hy) << 16) | __bfloat16_as_ushort(hx);
    l = ((unsigned)__bfloat16_as_ushort(ly) << 16) | __bfloat16_as_ushort(lx);
}

// ---------------- fp32 -> split bf16 conversion ----------------------------
__global__ void split_kernel(const float* __restrict__ src, int slot, int n)
{
    __nv_bfloat16 *h, *l;
    switch (slot) {
        case 0: h = gXh;           l = gXl;           break;
        case 1: h = gXh + NELEM;   l = gXl + NELEM;   break;
        case 2: h = gXh + 2*NELEM; l = gXl + 2*NELEM; break;
        case 3: h = gWh;           l = gWl;           break;
        case 4: h = gWh + WELEM;   l = gWl + WELEM;   break;
        case 5: h = gWh + 2*WELEM; l = gWl + 2*WELEM; break;
        default:h = gWh + 3*WELEM; l = gWl + 3*WELEM; break;
    }
    int n4 = n >> 2;
    for (int i = blockIdx.x * blockDim.x + threadIdx.x; i < n4;
         i += gridDim.x * blockDim.x) {
        float4 v = ((const float4*)src)[i];
        unsigned h0, l0, h1, l1;
        split_pack(v.x, v.y, h0, l0);
        split_pack(v.z, v.w, h1, l1);
        ((uint2*)h)[i] = make_uint2(h0, h1);
        ((uint2*)l)[i] = make_uint2(l0, l1);
    }
}

// ---------------- QKV projection GEMM (split bf16 tensor cores) ------------
// C = X(4096x1024) . W^T(1024x1024) + bias; scatter into (b,h,n,d) split bf16.
#define SAPAD 24   // 16 k-cols padded to 24 (48B rows; conflict-free ldmatrix)

__global__ __launch_bounds__(256, 2) void gemm_qkv(
    const float* __restrict__ bq, const float* __restrict__ bk,
    const float* __restrict__ bv)
{
    __shared__ __nv_bfloat16 sA[2][2][128*SAPAD];
    __shared__ __nv_bfloat16 sB[2][2][128*SAPAD];

    const int z = blockIdx.z;
    const __nv_bfloat16* Xh = gXh + (size_t)z * NELEM;
    const __nv_bfloat16* Xl = gXl + (size_t)z * NELEM;
    const __nv_bfloat16* Wh = gWh + (size_t)z * WELEM;
    const __nv_bfloat16* Wl = gWl + (size_t)z * WELEM;
    const float* bias = (z == 0) ? bq : (z == 1) ? bk : bv;
    __nv_bfloat16* Oh = (z == 0) ? gQh : (z == 1) ? gKh : gVh;
    __nv_bfloat16* Ol = (z == 0) ? gQl : (z == 1) ? gKl : gVl;
    const float scale = (z == 0) ? 0.125f : 1.0f;

    const int tid = threadIdx.x, lane = tid & 31, warp = tid >> 5;
    const int m0 = blockIdx.y * 128, n0 = blockIdx.x * 128;
    const int wm = (warp & 1) * 64, wn = (warp >> 1) * 32;

    const int lrow = tid >> 1, lch = (tid & 1) * 8;
    const __nv_bfloat16* gAh = Xh + (size_t)(m0 + lrow) * DM + lch;
    const __nv_bfloat16* gAl = Xl + (size_t)(m0 + lrow) * DM + lch;
    const __nv_bfloat16* gBh = Wh + (size_t)(n0 + lrow) * DM + lch;
    const __nv_bfloat16* gBl = Wl + (size_t)(n0 + lrow) * DM + lch;
    const int so = lrow * SAPAD + lch;

    float c[4][4][4];
    #pragma unroll
    for (int i = 0; i < 4; i++)
        #pragma unroll
        for (int j = 0; j < 4; j++)
            #pragma unroll
            for (int r = 0; r < 4; r++) c[i][j][r] = 0.0f;

    // prologue
    {
        cp16(&sA[0][0][so], gAh); cp16(&sA[0][1][so], gAl);
        cp16(&sB[0][0][so], gBh); cp16(&sB[0][1][so], gBl);
        CP_COMMIT();
    }

    const int ar = lane & 15, ac = (lane >> 4) * 8;
    const int br = lane & 7,  bc = ((lane >> 3) & 1) * 8;

    for (int kt = 0; kt < 64; kt++) {
        const int st = kt & 1;
        if (kt < 63) {
            int ko = (kt + 1) * 16;
            cp16(&sA[st ^ 1][0][so], gAh + ko); cp16(&sA[st ^ 1][1][so], gAl + ko);
            cp16(&sB[st ^ 1][0][so], gBh + ko); cp16(&sB[st ^ 1][1][so], gBl + ko);
        }
        CP_COMMIT();
        if (kt < 63) asm volatile("cp.async.wait_group 1;");
        else         asm volatile("cp.async.wait_group 0;");
        __syncthreads();

        unsigned bhf[4][2], blf[4][2];
        #pragma unroll
        for (int ni = 0; ni < 4; ni++) {
            int off = (wn + ni * 8 + br) * SAPAD + bc;
            ldm_x2(bhf[ni][0], bhf[ni][1], &sB[st][0][off]);
            ldm_x2(blf[ni][0], blf[ni][1], &sB[st][1][off]);
        }
        #pragma unroll
        for (int mi = 0; mi < 4; mi++) {
            unsigned ah[4], al[4];
            int off = (wm + mi * 16 + ar) * SAPAD + ac;
            ldm_x4(ah[0], ah[1], ah[2], ah[3], &sA[st][0][off]);
            ldm_x4(al[0], al[1], al[2], al[3], &sA[st][1][off]);
            #pragma unroll
            for (int ni = 0; ni < 4; ni++) {
                mma16816(c[mi][ni], ah[0], ah[1], ah[2], ah[3], bhf[ni][0], bhf[ni][1]);
                mma16816(c[mi][ni], ah[0], ah[1], ah[2], ah[3], blf[ni][0], blf[ni][1]);
                mma16816(c[mi][ni], al[0], al[1], al[2], al[3], bhf[ni][0], bhf[ni][1]);
            }
        }
        __syncthreads();
    }

    // epilogue: + bias, * scale(Q), split, scatter to (b,h,n,d)
    const int r0 = lane >> 2, cq = (lane & 3) * 2;
    #pragma unroll
    for (int mi = 0; mi < 4; mi++) {
        #pragma unroll
        for (int ni = 0; ni < 4; ni++) {
            int col = n0 + wn + ni * 8 + cq;
            float b0 = bias[col], b1 = bias[col + 1];
            int hh = col >> 6, d = col & 63;
            #pragma unroll
            for (int half = 0; half < 2; half++) {
                int row = m0 + wm + mi * 16 + r0 + half * 8;
                float v0 = (c[mi][ni][half * 2 + 0] + b0) * scale;
                float v1 = (c[mi][ni][half * 2 + 1] + b1) * scale;
                unsigned ph, pl;
                split_pack(v0, v1, ph, pl);
                int bb = row >> 11, n = row & (NSEQ - 1);
                size_t idx = (((size_t)(bb * NH + hh) * NSEQ + n) * HD + d);
                *(unsigned*)&Oh[idx] = ph;
                *(unsigned*)&Ol[idx] = pl;
            }
        }
    }
}

// ---------------- output projection GEMM -----------------------------------
__global__ __launch_bounds__(256, 2) void gemm_out(
    const float* __restrict__ bo, float* __restrict__ out)
{
    __shared__ __nv_bfloat16 sA[2][2][128*SAPAD];
    __shared__ __nv_bfloat16 sB[2][2][128*SAPAD];

    const __nv_bfloat16* Wh = gWh + 3 * WELEM;
    const __nv_bfloat16* Wl = gWl + 3 * WELEM;

    const int tid = threadIdx.x, lane = tid & 31, warp = tid >> 5;
    const int m0 = blockIdx.y * 128, n0 = blockIdx.x * 128;
    const int wm = (warp & 1) * 64, wn = (warp >> 1) * 32;

    const int lrow = tid >> 1, lch = (tid & 1) * 8;
    const __nv_bfloat16* gAh = gOh + (size_t)(m0 + lrow) * DM + lch;
    const __nv_bfloat16* gAl = gOl + (size_t)(m0 + lrow) * DM + lch;
    const __nv_bfloat16* gBh = Wh + (size_t)(n0 + lrow) * DM + lch;
    const __nv_bfloat16* gBl = Wl + (size_t)(n0 + lrow) * DM + lch;
    const int so = lrow * SAPAD + lch;

    float c[4][4][4];
    #pragma unroll
    for (int i = 0; i < 4; i++)
        #pragma unroll
        for (int j = 0; j < 4; j++)
            #pragma unroll
            for (int r = 0; r < 4; r++) c[i][j][r] = 0.0f;

    cp16(&sA[0][0][so], gAh); cp16(&sA[0][1][so], gAl);
    cp16(&sB[0][0][so], gBh); cp16(&sB[0][1][so], gBl);
    CP_COMMIT();

    const int ar = lane & 15, ac = (lane >> 4) * 8;
    const int br = lane & 7,  bc = ((lane >> 3) & 1) * 8;

    for (int kt = 0; kt < 64; kt++) {
        const int st = kt & 1;
        if (kt < 63) {
            int ko = (kt + 1) * 16;
            cp16(&sA[st ^ 1][0][so], gAh + ko); cp16(&sA[st ^ 1][1][so], gAl + ko);
            cp16(&sB[st ^ 1][0][so], gBh + ko); cp16(&sB[st ^ 1][1][so], gBl + ko);
        }
        CP_COMMIT();
        if (kt < 63) asm volatile("cp.async.wait_group 1;");
        else         asm volatile("cp.async.wait_group 0;");
        __syncthreads();

        unsigned bhf[4][2], blf[4][2];
        #pragma unroll
        for (int ni = 0; ni < 4; ni++) {
            int off = (wn + ni * 8 + br) * SAPAD + bc;
            ldm_x2(bhf[ni][0], bhf[ni][1], &sB[st][0][off]);
            ldm_x2(blf[ni][0], blf[ni][1], &sB[st][1][off]);
        }
        #pragma unroll
        for (int mi = 0; mi < 4; mi++) {
            unsigned ah[4], al[4];
            int off = (wm + mi * 16 + ar) * SAPAD + ac;
            ldm_x4(ah[0], ah[1], ah[2], ah[3], &sA[st][0][off]);
            ldm_x4(al[0], al[1], al[2], al[3], &sA[st][1][off]);
            #pragma unroll
            for (int ni = 0; ni < 4; ni++) {
                mma16816(c[mi][ni], ah[0], ah[1], ah[2], ah[3], bhf[ni][0], bhf[ni][1]);
                mma16816(c[mi][ni], ah[0], ah[1], ah[2], ah[3], blf[ni][0], blf[ni][1]);
                mma16816(c[mi][ni], al[0], al[1], al[2], al[3], bhf[ni][0], bhf[ni][1]);
            }
        }
        __syncthreads();
    }

    const int r0 = lane >> 2, cq = (lane & 3) * 2;
    #pragma unroll
    for (int mi = 0; mi < 4; mi++) {
        #pragma unroll
        for (int ni = 0; ni < 4; ni++) {
            int col = n0 + wn + ni * 8 + cq;
            float b0 = bo[col], b1 = bo[col + 1];
            #pragma unroll
            for (int half = 0; half < 2; half++) {
                int row = m0 + wm + mi * 16 + r0 + half * 8;
                float2 v = make_float2(c[mi][ni][half * 2 + 0] + b0,
                                       c[mi][ni][half * 2 + 1] + b1);
                *(float2*)&out[(size_t)row * DM + col] = v;
            }
        }
    }
}

// ---------------- flash attention (split bf16 tensor cores) ----------------
// CTA: 128 q-rows of one (b,h); 8 warps x 16 rows; 64-key tiles, double-buffered.
#define QPAD 72
#define KVSZ (64*QPAD)
#define FLASH_SMEM ((2*128*QPAD + 2*4*KVSZ) * 2)   // bytes = 110592

__global__ __launch_bounds__(256, 2) void flash()
{
    extern __shared__ __nv_bfloat16 sm[];
    __nv_bfloat16* sQh = sm;
    __nv_bfloat16* sQl = sm + 128 * QPAD;
    __nv_bfloat16* sKV = sm + 2 * 128 * QPAD;   // [stage][Kh,Kl,Vh,Vl][64*QPAD]

    const int tid = threadIdx.x, lane = tid & 31, warp = tid >> 5;
    const int bh = blockIdx.y, q0 = blockIdx.x * 128;
    const size_t base = (size_t)bh * NSEQ * HD;

    // Q tile load (once)
    #pragma unroll
    for (int u = 0; u < 4; u++) {
        int id = tid + u * 256;
        int r = id >> 3, ch = (id & 7) * 8;
        size_t g = base + (size_t)(q0 + r) * HD + ch;
        cp16(&sQh[r * QPAD + ch], gQh + g);
        cp16(&sQl[r * QPAD + ch], gQl + g);
    }
    CP_COMMIT();

    // K/V stage 0
    {
        __nv_bfloat16* d = sKV;
        #pragma unroll
        for (int u = 0; u < 2; u++) {
            int id = tid + u * 256;
            int r = id >> 3, ch = (id & 7) * 8;
            size_t g = base + (size_t)r * HD + ch;
            int s = r * QPAD + ch;
            cp16(d + s, gKh + g);            cp16(d + KVSZ + s, gKl + g);
            cp16(d + 2 * KVSZ + s, gVh + g); cp16(d + 3 * KVSZ + s, gVl + g);
        }
        CP_COMMIT();
    }

    float o[8][4];
    #pragma unroll
    for (int i = 0; i < 8; i++)
        #pragma unroll
        for (int j = 0; j < 4; j++) o[i][j] = 0.0f;
    float mr0 = -1e30f, mr1 = -1e30f, lr0 = 0.0f, lr1 = 0.0f;

    const int ar = lane & 15, ac = (lane >> 4) * 8;
    const int br = lane & 7,  bc = ((lane >> 3) & 1) * 8;

    for (int kt = 0; kt < NSEQ / 64; kt++) {
        const int st = kt & 1;
        if (kt < NSEQ / 64 - 1) {
            __nv_bfloat16* d = sKV + (st ^ 1) * 4 * KVSZ;
            size_t kb = base + (size_t)(kt + 1) * 64 * HD;
            #pragma unroll
            for (int u = 0; u < 2; u++) {
                int id = tid + u * 256;
                int r = id >> 3, ch = (id & 7) * 8;
                size_t g = kb + (size_t)r * HD + ch;
                int s = r * QPAD + ch;
                cp16(d + s, gKh + g);            cp16(d + KVSZ + s, gKl + g);
                cp16(d + 2 * KVSZ + s, gVh + g); cp16(d + 3 * KVSZ + s, gVl + g);
            }
        }
        CP_COMMIT();
        if (kt < NSEQ / 64 - 1) asm volatile("cp.async.wait_group 1;");
        else                    asm volatile("cp.async.wait_group 0;");
        __syncthreads();

        const __nv_bfloat16* Kh = sKV + st * 4 * KVSZ;
        const __nv_bfloat16* Kl = Kh + KVSZ;
        const __nv_bfloat16* Vh = Kh + 2 * KVSZ;
        const __nv_bfloat16* Vl = Kh + 3 * KVSZ;

        // S = Qscaled . K^T  (128x64 tile; this warp: 16 rows)
        float s[8][4];
        #pragma unroll
        for (int i = 0; i < 8; i++)
            #pragma unroll
            for (int j = 0; j < 4; j++) s[i][j] = 0.0f;

        #pragma unroll
        for (int kk = 0; kk < 4; kk++) {
            unsigned ah[4], al[4];
            int qoff = (warp * 16 + ar) * QPAD + kk * 16 + ac;
            ldm_x4(ah[0], ah[1], ah[2], ah[3], &sQh[qoff]);
            ldm_x4(al[0], al[1], al[2], al[3], &sQl[qoff]);
            #pragma unroll
            for (int ni = 0; ni < 8; ni++) {
                unsigned b0, b1, c0, c1;
                int koff = (ni * 8 + br) * QPAD + kk * 16 + bc;
                ldm_x2(b0, b1, &Kh[koff]);
                ldm_x2(c0, c1, &Kl[koff]);
                mma16816(s[ni], ah[0], ah[1], ah[2], ah[3], b0, b1);
                mma16816(s[ni], ah[0], ah[1], ah[2], ah[3], c0, c1);
                mma16816(s[ni], al[0], al[1], al[2], al[3], b0, b1);
            }
        }

        // online softmax (rows r0=lane/4, r1=r0+8 within warp tile)
        float mx0 = -1e30f, mx1 = -1e30f;
        #pragma unroll
        for (int ni = 0; ni < 8; ni++) {
            mx0 = fmaxf(mx0, fmaxf(s[ni][0], s[ni][1]));
            mx1 = fmaxf(mx1, fmaxf(s[ni][2], s[ni][3]));
        }
        mx0 = fmaxf(mx0, __shfl_xor_sync(0xffffffffu, mx0, 1));
        mx0 = fmaxf(mx0, __shfl_xor_sync(0xffffffffu, mx0, 2));
        mx1 = fmaxf(mx1, __shfl_xor_sync(0xffffffffu, mx1, 1));
        mx1 = fmaxf(mx1, __shfl_xor_sync(0xffffffffu, mx1, 2));

        float nm0 = fmaxf(mr0, mx0), nm1 = fmaxf(mr1, mx1);
        float cr0 = __expf(mr0 - nm0), cr1 = __expf(mr1 - nm1);
        mr0 = nm0; mr1 = nm1;

        float sum0 = 0.0f, sum1 = 0.0f;
        #pragma unroll
        for (int ni = 0; ni < 8; ni++) {
            s[ni][0] = __expf(s[ni][0] - nm0);
            s[ni][1] = __expf(s[ni][1] - nm0);
            s[ni][2] = __expf(s[ni][2] - nm1);
            s[ni][3] = __expf(s[ni][3] - nm1);
            sum0 += s[ni][0] + s[ni][1];
            sum1 += s[ni][2] + s[ni][3];
        }
        sum0 += __shfl_xor_sync(0xffffffffu, sum0, 1);
        sum0 += __shfl_xor_sync(0xffffffffu, sum0, 2);
        sum1 += __shfl_xor_sync(0xffffffffu, sum1, 1);
        sum1 += __shfl_xor_sync(0xffffffffu, sum1, 2);
        lr0 = lr0 * cr0 + sum0;
        lr1 = lr1 * cr1 + sum1;
        #pragma unroll
        for (int dj = 0; dj < 8; dj++) {
            o[dj][0] *= cr0; o[dj][1] *= cr0;
            o[dj][2] *= cr1; o[dj][3] *= cr1;
        }

        // O += P . V   (P repacked from s-frags, split bf16)
        #pragma unroll
        for (int kk = 0; kk < 4; kk++) {
            unsigned pah[4], pal[4];
            split_pack(s[2*kk][0],   s[2*kk][1],   pah[0], pal[0]);
            split_pack(s[2*kk][2],   s[2*kk][3],   pah[1], pal[1]);
            split_pack(s[2*kk+1][0], s[2*kk+1][1], pah[2], pal[2]);
            split_pack(s[2*kk+1][2], s[2*kk+1][3], pah[3], pal[3]);
            #pragma unroll
            for (int dj = 0; dj < 8; dj++) {
                unsigned vb0, vb1, vc0, vc1;
                int voff = (kk * 16 + ar) * QPAD + dj * 8;
                ldm_x2t(vb0, vb1, &Vh[voff]);
                ldm_x2t(vc0, vc1, &Vl[voff]);
                mma16816(o[dj], pah[0], pah[1], pah[2], pah[3], vb0, vb1);
                mma16816(o[dj], pah[0], pah[1], pah[2], pah[3], vc0, vc1);
                mma16816(o[dj], pal[0], pal[1], pal[2], pal[3], vb0, vb1);
            }
        }
        __syncthreads();
    }

    // epilogue: normalize, split, write to gO rows (b*n, h*64+d)
    const int b = bh >> 4, h = bh & 15;
    const int row0 = q0 + warp * 16 + (lane >> 2);
    const float inv0 = 1.0f / lr0, inv1 = 1.0f / lr1;
    const size_t rb = ((size_t)(b * NSEQ) + row0) * DM + h * HD;
    #pragma unroll
    for (int dj = 0; dj < 8; dj++) {
        int d = dj * 8 + (lane & 3) * 2;
        unsigned ph, pl;
        split_pack(o[dj][0] * inv0, o[dj][1] * inv0, ph, pl);
        *(unsigned*)&gOh[rb + d] = ph;
        *(unsigned*)&gOl[rb + d] = pl;
        split_pack(o[dj][2] * inv1, o[dj][3] * inv1, ph, pl);
        *(unsigned*)&gOh[rb + (size_t)8 * DM + d] = ph;
        *(unsigned*)&gOl[rb + (size_t)8 * DM + d] = pl;
    }
}

// ---------------------------------------------------------------------------
extern "C" void kernel_launch(void* const* d_in, const int* in_sizes, int n_in,
                              void* d_out, int out_size)
{
    (void)in_sizes; (void)n_in; (void)out_size;
    const float* queries = (const float*)d_in[0];
    const float* keys    = (const float*)d_in[1];
    const float* values  = (const float*)d_in[2];
    const float* Wq = (const float*)d_in[3];
    const float* bq = (const float*)d_in[4];
    const float* Wk = (const float*)d_in[5];
    const float* bk = (const float*)d_in[6];
    const float* Wv = (const float*)d_in[7];
    const float* bv = (const float*)d_in[8];
    const float* Wo = (const float*)d_in[9];
    const float* bo = (const float*)d_in[10];
    float* out = (float*)d_out;

    cudaFuncSetAttribute(flash, cudaFuncAttributeMaxDynamicSharedMemorySize,
                         FLASH_SMEM);

    // fp32 -> split bf16
    int nIn = (int)(MROWS * (size_t)DM);
    int nW  = (int)(DM * (size_t)DM);
    split_kernel<<<1024, 256>>>(queries, 0, nIn);
    split_kernel<<<1024, 256>>>(keys,    1, nIn);
    split_kernel<<<1024, 256>>>(values,  2, nIn);
    split_kernel<<<512, 256>>>(Wq, 3, nW);
    split_kernel<<<512, 256>>>(Wk, 4, nW);
    split_kernel<<<512, 256>>>(Wv, 5, nW);
    split_kernel<<<512, 256>>>(Wo, 6, nW);

    // QKV projections
    gemm_qkv<<<dim3(DM / 128, MROWS / 128, 3), 256>>>(bq, bk, bv);

    // attention
    flash<<<dim3(NSEQ / 128, NB * NH), 256, FLASH_SMEM>>>();

    // output projection
    gemm_out<<<dim3(DM / 128, MROWS / 128), 256>>>(bo, out);
}

// round 4
// speedup vs baseline: 2.9602x; 1.1075x over previous
#include <cuda_runtime.h>
#include <cuda_bf16.h>
#include <cuda_fp16.h>
#include <math.h>
#include <stdint.h>

#define DM   1024
#define NSEQ 2048
#define NB   2
#define NH   16
#define HD   64
#define MROWS (NB*NSEQ)          // 4096
#define NELEM ((size_t)MROWS*DM) // 4,194,304
#define WELEM ((size_t)DM*DM)    // 1,048,576

// ---------------- scratch (__device__ globals; no allocations) -------------
__device__ __nv_bfloat16 gXh[3*NELEM];   // split inputs q,k,v
__device__ __nv_bfloat16 gXl[3*NELEM];
__device__ __nv_bfloat16 gWh[4*WELEM];   // split weights Wq,Wk,Wv,Wo
__device__ __nv_bfloat16 gWl[4*WELEM];
__device__ __nv_bfloat16 gQh[NELEM], gQl[NELEM];  // (b,h,n,d), Q pre-scaled
__device__ __nv_bfloat16 gKh[NELEM], gKl[NELEM];
__device__ __half        gVh16[NELEM], gVl16[NELEM]; // V as fp16 pair
__device__ __nv_bfloat16 gOh[NELEM], gOl[NELEM];  // attn out (b*n, h*d)

// ---------------- PTX helpers ---------------------------------------------
__device__ __forceinline__ void mma16816(float* c,
    unsigned a0, unsigned a1, unsigned a2, unsigned a3,
    unsigned b0, unsigned b1)
{
    asm volatile(
        "mma.sync.aligned.m16n8k16.row.col.f32.bf16.bf16.f32 "
        "{%0,%1,%2,%3},{%4,%5,%6,%7},{%8,%9},{%0,%1,%2,%3};"
        : "+f"(c[0]), "+f"(c[1]), "+f"(c[2]), "+f"(c[3])
        : "r"(a0), "r"(a1), "r"(a2), "r"(a3), "r"(b0), "r"(b1));
}

__device__ __forceinline__ void mma16816h(float* c,
    unsigned a0, unsigned a1, unsigned a2, unsigned a3,
    unsigned b0, unsigned b1)
{
    asm volatile(
        "mma.sync.aligned.m16n8k16.row.col.f32.f16.f16.f32 "
        "{%0,%1,%2,%3},{%4,%5,%6,%7},{%8,%9},{%0,%1,%2,%3};"
        : "+f"(c[0]), "+f"(c[1]), "+f"(c[2]), "+f"(c[3])
        : "r"(a0), "r"(a1), "r"(a2), "r"(a3), "r"(b0), "r"(b1));
}

__device__ __forceinline__ void ldm_x4(unsigned& r0, unsigned& r1,
                                       unsigned& r2, unsigned& r3,
                                       const void* p)
{
    unsigned a = (unsigned)__cvta_generic_to_shared(p);
    asm volatile("ldmatrix.sync.aligned.m8n8.x4.shared.b16 {%0,%1,%2,%3},[%4];"
                 : "=r"(r0), "=r"(r1), "=r"(r2), "=r"(r3) : "r"(a));
}

__device__ __forceinline__ void ldm_x2(unsigned& r0, unsigned& r1, const void* p)
{
    unsigned a = (unsigned)__cvta_generic_to_shared(p);
    asm volatile("ldmatrix.sync.aligned.m8n8.x2.shared.b16 {%0,%1},[%2];"
                 : "=r"(r0), "=r"(r1) : "r"(a));
}

__device__ __forceinline__ void ldm_x2t(unsigned& r0, unsigned& r1, const void* p)
{
    unsigned a = (unsigned)__cvta_generic_to_shared(p);
    asm volatile("ldmatrix.sync.aligned.m8n8.x2.trans.shared.b16 {%0,%1},[%2];"
                 : "=r"(r0), "=r"(r1) : "r"(a));
}

__device__ __forceinline__ void cp16(void* dst, const void* src)
{
    unsigned d = (unsigned)__cvta_generic_to_shared(dst);
    asm volatile("cp.async.cg.shared.global [%0], [%1], 16;" :: "r"(d), "l"(src));
}
#define CP_COMMIT() asm volatile("cp.async.commit_group;")

// split fp32 pair -> packed bf16x2 hi + bf16x2 lo
__device__ __forceinline__ void split_pack(float x, float y,
                                           unsigned& h, unsigned& l)
{
    __nv_bfloat16 hx = __float2bfloat16(x);
    __nv_bfloat16 hy = __float2bfloat16(y);
    float rx = x - __bfloat162float(hx);
    float ry = y - __bfloat162float(hy);
    __nv_bfloat16 lx = __float2bfloat16(rx);
    __nv_bfloat16 ly = __float2bfloat16(ry);
    h = ((unsigned)__bfloat16_as_ushort(hy) << 16) | __bfloat16_as_ushort(hx);
    l = ((unsigned)__bfloat16_as_ushort(ly) << 16) | __bfloat16_as_ushort(lx);
}

// split fp32 pair -> packed fp16x2 hi + fp16x2 lo
__device__ __forceinline__ void split_pack_h(float x, float y,
                                             unsigned& h, unsigned& l)
{
    __half hx = __float2half_rn(x);
    __half hy = __float2half_rn(y);
    float rx = x - __half2float(hx);
    float ry = y - __half2float(hy);
    __half2 hp = __halves2half2(hx, hy);
    __half2 lp = __halves2half2(__float2half_rn(rx), __float2half_rn(ry));
    h = *(unsigned*)&hp;
    l = *(unsigned*)&lp;
}

__device__ __forceinline__ unsigned pack_h2(float x, float y)
{
    __half2 p = __floats2half2_rn(x, y);
    return *(unsigned*)&p;
}

// ---------------- merged fp32 -> split bf16 conversion (single launch) -----
#define NF4_IN (NELEM >> 2)   // 2^20 float4 per input tensor
#define NF4_W  (WELEM >> 2)   // 2^18 float4 per weight tensor
#define NF4_TOT (3*NF4_IN + 4*NF4_W)

__global__ void split_all(const float* __restrict__ q, const float* __restrict__ k,
                          const float* __restrict__ v, const float* __restrict__ wq,
                          const float* __restrict__ wk, const float* __restrict__ wv,
                          const float* __restrict__ wo)
{
    for (size_t i = blockIdx.x * blockDim.x + threadIdx.x; i < NF4_TOT;
         i += (size_t)gridDim.x * blockDim.x) {
        const float* src;
        __nv_bfloat16 *h, *l;
        size_t off;
        if (i < 3*NF4_IN) {
            int slot = (int)(i >> 20);
            off = i & (NF4_IN - 1);
            src = (slot == 0) ? q : (slot == 1) ? k : v;
            h = gXh + (size_t)slot * NELEM;
            l = gXl + (size_t)slot * NELEM;
        } else {
            size_t j = i - 3*NF4_IN;
            int slot = (int)(j >> 18);
            off = j & (NF4_W - 1);
            src = (slot == 0) ? wq : (slot == 1) ? wk : (slot == 2) ? wv : wo;
            h = gWh + (size_t)slot * WELEM;
            l = gWl + (size_t)slot * WELEM;
        }
        float4 val = ((const float4*)src)[off];
        unsigned h0, l0, h1, l1;
        split_pack(val.x, val.y, h0, l0);
        split_pack(val.z, val.w, h1, l1);
        ((uint2*)h)[off] = make_uint2(h0, h1);
        ((uint2*)l)[off] = make_uint2(l0, l1);
    }
}

// ---------------- QKV projection GEMM (split bf16 tensor cores) ------------
#define SAPAD 24

__global__ __launch_bounds__(256, 2) void gemm_qkv(
    const float* __restrict__ bq, const float* __restrict__ bk,
    const float* __restrict__ bv)
{
    __shared__ __nv_bfloat16 sA[2][2][128*SAPAD];
    __shared__ __nv_bfloat16 sB[2][2][128*SAPAD];

    const int z = blockIdx.z;
    const __nv_bfloat16* Xh = gXh + (size_t)z * NELEM;
    const __nv_bfloat16* Xl = gXl + (size_t)z * NELEM;
    const __nv_bfloat16* Wh = gWh + (size_t)z * WELEM;
    const __nv_bfloat16* Wl = gWl + (size_t)z * WELEM;
    const float* bias = (z == 0) ? bq : (z == 1) ? bk : bv;
    const float scale = (z == 0) ? 0.125f : 1.0f;

    const int tid = threadIdx.x, lane = tid & 31, warp = tid >> 5;
    const int m0 = blockIdx.y * 128, n0 = blockIdx.x * 128;
    const int wm = (warp & 1) * 64, wn = (warp >> 1) * 32;

    const int lrow = tid >> 1, lch = (tid & 1) * 8;
    const __nv_bfloat16* gAh = Xh + (size_t)(m0 + lrow) * DM + lch;
    const __nv_bfloat16* gAl = Xl + (size_t)(m0 + lrow) * DM + lch;
    const __nv_bfloat16* gBh = Wh + (size_t)(n0 + lrow) * DM + lch;
    const __nv_bfloat16* gBl = Wl + (size_t)(n0 + lrow) * DM + lch;
    const int so = lrow * SAPAD + lch;

    float c[4][4][4];
    #pragma unroll
    for (int i = 0; i < 4; i++)
        #pragma unroll
        for (int j = 0; j < 4; j++)
            #pragma unroll
            for (int r = 0; r < 4; r++) c[i][j][r] = 0.0f;

    cp16(&sA[0][0][so], gAh); cp16(&sA[0][1][so], gAl);
    cp16(&sB[0][0][so], gBh); cp16(&sB[0][1][so], gBl);
    CP_COMMIT();

    const int ar = lane & 15, ac = (lane >> 4) * 8;
    const int br = lane & 7,  bc = ((lane >> 3) & 1) * 8;

    for (int kt = 0; kt < 64; kt++) {
        const int st = kt & 1;
        if (kt < 63) {
            int ko = (kt + 1) * 16;
            cp16(&sA[st ^ 1][0][so], gAh + ko); cp16(&sA[st ^ 1][1][so], gAl + ko);
            cp16(&sB[st ^ 1][0][so], gBh + ko); cp16(&sB[st ^ 1][1][so], gBl + ko);
        }
        CP_COMMIT();
        if (kt < 63) asm volatile("cp.async.wait_group 1;");
        else         asm volatile("cp.async.wait_group 0;");
        __syncthreads();

        unsigned bhf[4][2], blf[4][2];
        #pragma unroll
        for (int ni = 0; ni < 4; ni++) {
            int off = (wn + ni * 8 + br) * SAPAD + bc;
            ldm_x2(bhf[ni][0], bhf[ni][1], &sB[st][0][off]);
            ldm_x2(blf[ni][0], blf[ni][1], &sB[st][1][off]);
        }
        #pragma unroll
        for (int mi = 0; mi < 4; mi++) {
            unsigned ah[4], al[4];
            int off = (wm + mi * 16 + ar) * SAPAD + ac;
            ldm_x4(ah[0], ah[1], ah[2], ah[3], &sA[st][0][off]);
            ldm_x4(al[0], al[1], al[2], al[3], &sA[st][1][off]);
            #pragma unroll
            for (int ni = 0; ni < 4; ni++) {
                mma16816(c[mi][ni], ah[0], ah[1], ah[2], ah[3], bhf[ni][0], bhf[ni][1]);
                mma16816(c[mi][ni], ah[0], ah[1], ah[2], ah[3], blf[ni][0], blf[ni][1]);
                mma16816(c[mi][ni], al[0], al[1], al[2], al[3], bhf[ni][0], bhf[ni][1]);
            }
        }
        __syncthreads();
    }

    // epilogue: + bias, * scale(Q), split, scatter to (b,h,n,d)
    const int r0 = lane >> 2, cq = (lane & 3) * 2;
    #pragma unroll
    for (int mi = 0; mi < 4; mi++) {
        #pragma unroll
        for (int ni = 0; ni < 4; ni++) {
            int col = n0 + wn + ni * 8 + cq;
            float b0 = bias[col], b1 = bias[col + 1];
            int hh = col >> 6, d = col & 63;
            #pragma unroll
            for (int half = 0; half < 2; half++) {
                int row = m0 + wm + mi * 16 + r0 + half * 8;
                float v0 = (c[mi][ni][half * 2 + 0] + b0) * scale;
                float v1 = (c[mi][ni][half * 2 + 1] + b1) * scale;
                int bb = row >> 11, n = row & (NSEQ - 1);
                size_t idx = (((size_t)(bb * NH + hh)) * NSEQ + n) * HD + d;
                unsigned ph, pl;
                if (z == 2) {
                    split_pack_h(v0, v1, ph, pl);
                    *(unsigned*)&gVh16[idx] = ph;
                    *(unsigned*)&gVl16[idx] = pl;
                } else {
                    split_pack(v0, v1, ph, pl);
                    if (z == 0) { *(unsigned*)&gQh[idx] = ph; *(unsigned*)&gQl[idx] = pl; }
                    else        { *(unsigned*)&gKh[idx] = ph; *(unsigned*)&gKl[idx] = pl; }
                }
            }
        }
    }
}

// ---------------- output projection GEMM (split bf16, 3-term) --------------
__global__ __launch_bounds__(256, 2) void gemm_out(
    const float* __restrict__ bo, float* __restrict__ out)
{
    __shared__ __nv_bfloat16 sA[2][2][128*SAPAD];
    __shared__ __nv_bfloat16 sB[2][2][128*SAPAD];

    const __nv_bfloat16* Wh = gWh + 3 * WELEM;
    const __nv_bfloat16* Wl = gWl + 3 * WELEM;

    const int tid = threadIdx.x, lane = tid & 31, warp = tid >> 5;
    const int m0 = blockIdx.y * 128, n0 = blockIdx.x * 128;
    const int wm = (warp & 1) * 64, wn = (warp >> 1) * 32;

    const int lrow = tid >> 1, lch = (tid & 1) * 8;
    const __nv_bfloat16* gAh = gOh + (size_t)(m0 + lrow) * DM + lch;
    const __nv_bfloat16* gAl = gOl + (size_t)(m0 + lrow) * DM + lch;
    const __nv_bfloat16* gBh = Wh + (size_t)(n0 + lrow) * DM + lch;
    const __nv_bfloat16* gBl = Wl + (size_t)(n0 + lrow) * DM + lch;
    const int so = lrow * SAPAD + lch;

    float c[4][4][4];
    #pragma unroll
    for (int i = 0; i < 4; i++)
        #pragma unroll
        for (int j = 0; j < 4; j++)
            #pragma unroll
            for (int r = 0; r < 4; r++) c[i][j][r] = 0.0f;

    cp16(&sA[0][0][so], gAh); cp16(&sA[0][1][so], gAl);
    cp16(&sB[0][0][so], gBh); cp16(&sB[0][1][so], gBl);
    CP_COMMIT();

    const int ar = lane & 15, ac = (lane >> 4) * 8;
    const int br = lane & 7,  bc = ((lane >> 3) & 1) * 8;

    for (int kt = 0; kt < 64; kt++) {
        const int st = kt & 1;
        if (kt < 63) {
            int ko = (kt + 1) * 16;
            cp16(&sA[st ^ 1][0][so], gAh + ko); cp16(&sA[st ^ 1][1][so], gAl + ko);
            cp16(&sB[st ^ 1][0][so], gBh + ko); cp16(&sB[st ^ 1][1][so], gBl + ko);
        }
        CP_COMMIT();
        if (kt < 63) asm volatile("cp.async.wait_group 1;");
        else         asm volatile("cp.async.wait_group 0;");
        __syncthreads();

        unsigned bhf[4][2], blf[4][2];
        #pragma unroll
        for (int ni = 0; ni < 4; ni++) {
            int off = (wn + ni * 8 + br) * SAPAD + bc;
            ldm_x2(bhf[ni][0], bhf[ni][1], &sB[st][0][off]);
            ldm_x2(blf[ni][0], blf[ni][1], &sB[st][1][off]);
        }
        #pragma unroll
        for (int mi = 0; mi < 4; mi++) {
            unsigned ah[4], al[4];
            int off = (wm + mi * 16 + ar) * SAPAD + ac;
            ldm_x4(ah[0], ah[1], ah[2], ah[3], &sA[st][0][off]);
            ldm_x4(al[0], al[1], al[2], al[3], &sA[st][1][off]);
            #pragma unroll
            for (int ni = 0; ni < 4; ni++) {
                mma16816(c[mi][ni], ah[0], ah[1], ah[2], ah[3], bhf[ni][0], bhf[ni][1]);
                mma16816(c[mi][ni], ah[0], ah[1], ah[2], ah[3], blf[ni][0], blf[ni][1]);
                mma16816(c[mi][ni], al[0], al[1], al[2], al[3], bhf[ni][0], bhf[ni][1]);
            }
        }
        __syncthreads();
    }

    const int r0 = lane >> 2, cq = (lane & 3) * 2;
    #pragma unroll
    for (int mi = 0; mi < 4; mi++) {
        #pragma unroll
        for (int ni = 0; ni < 4; ni++) {
            int col = n0 + wn + ni * 8 + cq;
            float b0 = bo[col], b1 = bo[col + 1];
            #pragma unroll
            for (int half = 0; half < 2; half++) {
                int row = m0 + wm + mi * 16 + r0 + half * 8;
                float2 v = make_float2(c[mi][ni][half * 2 + 0] + b0,
                                       c[mi][ni][half * 2 + 1] + b1);
                *(float2*)&out[(size_t)row * DM + col] = v;
            }
        }
    }
}

// ---------------- flash attention -------------------------------------------
// S: 3-term split bf16. PV: P fp16-single x V fp16-pair (2 MMAs).
#define QPAD 72
#define KVSZ (64*QPAD)
#define FLASH_SMEM ((2*128*QPAD + 2*4*KVSZ) * 2)   // bytes = 110592

__global__ __launch_bounds__(256, 2) void flash()
{
    extern __shared__ __nv_bfloat16 sm[];
    __nv_bfloat16* sQh = sm;
    __nv_bfloat16* sQl = sm + 128 * QPAD;
    __nv_bfloat16* sKV = sm + 2 * 128 * QPAD;   // [stage][Kh,Kl,Vh,Vl][64*QPAD]

    const int tid = threadIdx.x, lane = tid & 31, warp = tid >> 5;
    const int bh = blockIdx.y, q0 = blockIdx.x * 128;
    const size_t base = (size_t)bh * NSEQ * HD;

    #pragma unroll
    for (int u = 0; u < 4; u++) {
        int id = tid + u * 256;
        int r = id >> 3, ch = (id & 7) * 8;
        size_t g = base + (size_t)(q0 + r) * HD + ch;
        cp16(&sQh[r * QPAD + ch], gQh + g);
        cp16(&sQl[r * QPAD + ch], gQl + g);
    }
    CP_COMMIT();

    {
        __nv_bfloat16* d = sKV;
        #pragma unroll
        for (int u = 0; u < 2; u++) {
            int id = tid + u * 256;
            int r = id >> 3, ch = (id & 7) * 8;
            size_t g = base + (size_t)r * HD + ch;
            int s = r * QPAD + ch;
            cp16(d + s, gKh + g);            cp16(d + KVSZ + s, gKl + g);
            cp16(d + 2 * KVSZ + s, gVh16 + g); cp16(d + 3 * KVSZ + s, gVl16 + g);
        }
        CP_COMMIT();
    }

    float o[8][4];
    #pragma unroll
    for (int i = 0; i < 8; i++)
        #pragma unroll
        for (int j = 0; j < 4; j++) o[i][j] = 0.0f;
    float mr0 = -1e30f, mr1 = -1e30f, lr0 = 0.0f, lr1 = 0.0f;

    const int ar = lane & 15, ac = (lane >> 4) * 8;
    const int br = lane & 7,  bc = ((lane >> 3) & 1) * 8;

    for (int kt = 0; kt < NSEQ / 64; kt++) {
        const int st = kt & 1;
        if (kt < NSEQ / 64 - 1) {
            __nv_bfloat16* d = sKV + (st ^ 1) * 4 * KVSZ;
            size_t kb = base + (size_t)(kt + 1) * 64 * HD;
            #pragma unroll
            for (int u = 0; u < 2; u++) {
                int id = tid + u * 256;
                int r = id >> 3, ch = (id & 7) * 8;
                size_t g = kb + (size_t)r * HD + ch;
                int s = r * QPAD + ch;
                cp16(d + s, gKh + g);            cp16(d + KVSZ + s, gKl + g);
                cp16(d + 2 * KVSZ + s, gVh16 + g); cp16(d + 3 * KVSZ + s, gVl16 + g);
            }
        }
        CP_COMMIT();
        if (kt < NSEQ / 64 - 1) asm volatile("cp.async.wait_group 1;");
        else                    asm volatile("cp.async.wait_group 0;");
        __syncthreads();

        const __nv_bfloat16* Kh = sKV + st * 4 * KVSZ;
        const __nv_bfloat16* Kl = Kh + KVSZ;
        const __half* Vh = (const __half*)(Kh + 2 * KVSZ);
        const __half* Vl = (const __half*)(Kh + 3 * KVSZ);

        float s[8][4];
        #pragma unroll
        for (int i = 0; i < 8; i++)
            #pragma unroll
            for (int j = 0; j < 4; j++) s[i][j] = 0.0f;

        #pragma unroll
        for (int kk = 0; kk < 4; kk++) {
            unsigned ah[4], al[4];
            int qoff = (warp * 16 + ar) * QPAD + kk * 16 + ac;
            ldm_x4(ah[0], ah[1], ah[2], ah[3], &sQh[qoff]);
            ldm_x4(al[0], al[1], al[2], al[3], &sQl[qoff]);
            #pragma unroll
            for (int ni = 0; ni < 8; ni++) {
                unsigned b0, b1, c0, c1;
                int koff = (ni * 8 + br) * QPAD + kk * 16 + bc;
                ldm_x2(b0, b1, &Kh[koff]);
                ldm_x2(c0, c1, &Kl[koff]);
                mma16816(s[ni], ah[0], ah[1], ah[2], ah[3], b0, b1);
                mma16816(s[ni], ah[0], ah[1], ah[2], ah[3], c0, c1);
                mma16816(s[ni], al[0], al[1], al[2], al[3], b0, b1);
            }
        }

        float mx0 = -1e30f, mx1 = -1e30f;
        #pragma unroll
        for (int ni = 0; ni < 8; ni++) {
            mx0 = fmaxf(mx0, fmaxf(s[ni][0], s[ni][1]));
            mx1 = fmaxf(mx1, fmaxf(s[ni][2], s[ni][3]));
        }
        mx0 = fmaxf(mx0, __shfl_xor_sync(0xffffffffu, mx0, 1));
        mx0 = fmaxf(mx0, __shfl_xor_sync(0xffffffffu, mx0, 2));
        mx1 = fmaxf(mx1, __shfl_xor_sync(0xffffffffu, mx1, 1));
        mx1 = fmaxf(mx1, __shfl_xor_sync(0xffffffffu, mx1, 2));

        float nm0 = fmaxf(mr0, mx0), nm1 = fmaxf(mr1, mx1);
        float cr0 = __expf(mr0 - nm0), cr1 = __expf(mr1 - nm1);
        mr0 = nm0; mr1 = nm1;

        float sum0 = 0.0f, sum1 = 0.0f;
        #pragma unroll
        for (int ni = 0; ni < 8; ni++) {
            s[ni][0] = __expf(s[ni][0] - nm0);
            s[ni][1] = __expf(s[ni][1] - nm0);
            s[ni][2] = __expf(s[ni][2] - nm1);
            s[ni][3] = __expf(s[ni][3] - nm1);
            sum0 += s[ni][0] + s[ni][1];
            sum1 += s[ni][2] + s[ni][3];
        }
        sum0 += __shfl_xor_sync(0xffffffffu, sum0, 1);
        sum0 += __shfl_xor_sync(0xffffffffu, sum0, 2);
        sum1 += __shfl_xor_sync(0xffffffffu, sum1, 1);
        sum1 += __shfl_xor_sync(0xffffffffu, sum1, 2);
        lr0 = lr0 * cr0 + sum0;
        lr1 = lr1 * cr1 + sum1;
        #pragma unroll
        for (int dj = 0; dj < 8; dj++) {
            o[dj][0] *= cr0; o[dj][1] *= cr0;
            o[dj][2] *= cr1; o[dj][3] *= cr1;
        }

        // O += P(fp16) . V(fp16 hi+lo): 2 MMAs per 16x8 tile
        #pragma unroll
        for (int kk = 0; kk < 4; kk++) {
            unsigned p0 = pack_h2(s[2*kk][0],   s[2*kk][1]);
            unsigned p1 = pack_h2(s[2*kk][2],   s[2*kk][3]);
            unsigned p2 = pack_h2(s[2*kk+1][0], s[2*kk+1][1]);
            unsigned p3 = pack_h2(s[2*kk+1][2], s[2*kk+1][3]);
            #pragma unroll
            for (int dj = 0; dj < 8; dj++) {
                unsigned vb0, vb1, vc0, vc1;
                int voff = (kk * 16 + ar) * QPAD + dj * 8;
                ldm_x2t(vb0, vb1, &Vh[voff]);
                ldm_x2t(vc0, vc1, &Vl[voff]);
                mma16816h(o[dj], p0, p1, p2, p3, vb0, vb1);
                mma16816h(o[dj], p0, p1, p2, p3, vc0, vc1);
            }
        }
        __syncthreads();
    }

    const int b = bh >> 4, h = bh & 15;
    const int row0 = q0 + warp * 16 + (lane >> 2);
    const float inv0 = 1.0f / lr0, inv1 = 1.0f / lr1;
    const size_t rb = ((size_t)(b * NSEQ) + row0) * DM + h * HD;
    #pragma unroll
    for (int dj = 0; dj < 8; dj++) {
        int d = dj * 8 + (lane & 3) * 2;
        unsigned ph, pl;
        split_pack(o[dj][0] * inv0, o[dj][1] * inv0, ph, pl);
        *(unsigned*)&gOh[rb + d] = ph;
        *(unsigned*)&gOl[rb + d] = pl;
        split_pack(o[dj][2] * inv1, o[dj][3] * inv1, ph, pl);
        *(unsigned*)&gOh[rb + (size_t)8 * DM + d] = ph;
        *(unsigned*)&gOl[rb + (size_t)8 * DM + d] = pl;
    }
}

// ---------------------------------------------------------------------------
extern "C" void kernel_launch(void* const* d_in, const int* in_sizes, int n_in,
                              void* d_out, int out_size)
{
    (void)in_sizes; (void)n_in; (void)out_size;
    const float* queries = (const float*)d_in[0];
    const float* keys    = (const float*)d_in[1];
    const float* values  = (const float*)d_in[2];
    const float* Wq = (const float*)d_in[3];
    const float* bq = (const float*)d_in[4];
    const float* Wk = (const float*)d_in[5];
    const float* bk = (const float*)d_in[6];
    const float* Wv = (const float*)d_in[7];
    const float* bv = (const float*)d_in[8];
    const float* Wo = (const float*)d_in[9];
    const float* bo = (const float*)d_in[10];
    float* out = (float*)d_out;

    cudaFuncSetAttribute(flash, cudaFuncAttributeMaxDynamicSharedMemorySize,
                         FLASH_SMEM);

    // fp32 -> split bf16 (single launch)
    split_all<<<2048, 256>>>(queries, keys, values, Wq, Wk, Wv, Wo);

    // QKV projections
    gemm_qkv<<<dim3(DM / 128, MROWS / 128, 3), 256>>>(bq, bk, bv);

    // attention
    flash<<<dim3(NSEQ / 128, NB * NH), 256, FLASH_SMEM>>>();

    // output projection
    gemm_out<<<dim3(DM / 128, MROWS / 128), 256>>>(bo, out);
}